// round 10
// baseline (speedup 1.0000x reference)
#include <cuda_runtime.h>
#include <cuda_fp16.h>
#include <mma.h>
#include <math.h>

using namespace nvcuda;

#define NN    100000
#define EE    1600000
#define EAT   1700000   // EE + NN self loops
#define GGR   128
#define IN_F  16
#define HIDC  32
#define NHEADS 4
#define EDIMC 8
#define HCC   128
#define OUTC  4

typedef unsigned long long u64;

// ---------------- scratch (device globals: no allocation allowed) ----------
__device__ __half   d_xlh [NN * HCC];
__device__ float    d_xr  [NN * HCC];
__device__ float    d_hin [NN * HCC];
__device__ __half   d_hinh[NN * HCC];
__device__ float    d_loop[NN * EDIMC];
__device__ int      d_deg [NN];
__device__ int      d_off [NN + 1];
__device__ int      d_cur [NN];
__device__ int      d_psrc[EAT];
__device__ uint4    d_peah[EAT];
__device__ __half   d_wh1 [IN_F * 2 * HCC];
__device__ __half   d_wh2 [HCC * 2 * HCC];
__device__ __half   d_wh3 [HCC * 2 * HIDC];
__device__ float    d_gsum[GGR * HIDC];
__device__ float    d_gcnt[GGR];

// ---------------- helpers ---------------------------------------------------
__device__ __forceinline__ void atomAdd4(float4* p, float4 v) { atomicAdd(p, v); }
__device__ __forceinline__ float eluf(float x) { return x > 0.0f ? x : (__expf(x) - 1.0f); }
__device__ __forceinline__ float lrelu(float x) { return x > 0.0f ? x : 0.2f * x; }
__device__ __forceinline__ unsigned h2u(__half2 h) { return *reinterpret_cast<unsigned*>(&h); }
__device__ __forceinline__ __half2  u2h(unsigned u) { return *reinterpret_cast<__half2*>(&u); }

// packed f32x2 helpers (sm_103a dual-rate fp32)
__device__ __forceinline__ u64 pk(float lo, float hi) {
    u64 r; asm("mov.b64 %0, {%1, %2};" : "=l"(r) : "f"(lo), "f"(hi)); return r;
}
__device__ __forceinline__ float2 upk(u64 v) {
    float2 f; asm("mov.b64 {%0, %1}, %2;" : "=f"(f.x), "=f"(f.y) : "l"(v)); return f;
}
__device__ __forceinline__ u64 fma2(u64 a, u64 b, u64 c) {
    u64 r; asm("fma.rn.f32x2 %0, %1, %2, %3;" : "=l"(r) : "l"(a), "l"(b), "l"(c)); return r;
}
__device__ __forceinline__ u64 add2(u64 a, u64 b) {
    u64 r; asm("add.rn.f32x2 %0, %1, %2;" : "=l"(r) : "l"(a), "l"(b)); return r;
}

__device__ __forceinline__ uint4 pack8h(float4 a, float4 b) {
    uint4 o;
    o.x = h2u(__floats2half2_rn(a.x, a.y));
    o.y = h2u(__floats2half2_rn(a.z, a.w));
    o.z = h2u(__floats2half2_rn(b.x, b.y));
    o.w = h2u(__floats2half2_rn(b.z, b.w));
    return o;
}

// ---------------- utility kernels -------------------------------------------
__global__ void k_fill4(float4* __restrict__ p, float v, int n4) {
    int i = blockIdx.x * blockDim.x + threadIdx.x;
    if (i < n4) p[i] = make_float4(v, v, v, v);
}

__global__ void k_hist(const int* __restrict__ dst, const float* __restrict__ eattr,
                       int* __restrict__ deg, float* __restrict__ loop) {
    int e = blockIdx.x * blockDim.x + threadIdx.x;
    if (e >= EE) return;
    int d = dst[e];
    atomicAdd(&deg[d], 1);
    const float4* ea4 = reinterpret_cast<const float4*>(eattr) + (size_t)e * 2;
    float4* l4 = reinterpret_cast<float4*>(loop) + (size_t)d * 2;
    atomAdd4(&l4[0], ea4[0]);
    atomAdd4(&l4[1], ea4[1]);
}

__global__ void k_loop_div(float* __restrict__ loop, const int* __restrict__ deg) {
    int idx = blockIdx.x * blockDim.x + threadIdx.x;
    if (idx >= NN * 2) return;
    int i = idx >> 1;
    float inv = 1.0f / fmaxf((float)deg[i], 1.0f);
    float4* l4 = reinterpret_cast<float4*>(loop);
    float4 v = l4[idx];
    v.x *= inv; v.y *= inv; v.z *= inv; v.w *= inv;
    l4[idx] = v;
}

__global__ void __launch_bounds__(1024)
k_scan(const int* __restrict__ deg, int* __restrict__ off, int* __restrict__ cur) {
    __shared__ int part[1024];
    const int t = threadIdx.x;
    const int CH = (NN + 1023) / 1024;
    int b = t * CH;
    int e2 = b + CH; if (e2 > NN) e2 = NN;
    int s = 0;
    for (int i = b; i < e2; i++) s += deg[i] + 1;
    part[t] = s;
    __syncthreads();
    for (int d = 1; d < 1024; d <<= 1) {
        int v = (t >= d) ? part[t - d] : 0;
        __syncthreads();
        part[t] += v;
        __syncthreads();
    }
    int run = part[t] - s;
    for (int i = b; i < e2; i++) {
        off[i] = run;
        cur[i] = run + 1;
        run += deg[i] + 1;
    }
    if (t == 1023) off[NN] = part[1023];
}

__global__ void k_self(const int* __restrict__ off, const float* __restrict__ loop,
                       int* __restrict__ psrc, uint4* __restrict__ peah) {
    int i = blockIdx.x * blockDim.x + threadIdx.x;
    if (i >= NN) return;
    int p = off[i];
    psrc[p] = i;
    const float4* l4 = reinterpret_cast<const float4*>(loop) + (size_t)i * 2;
    peah[p] = pack8h(l4[0], l4[1]);
}

__global__ void k_scatter(const int* __restrict__ src, const int* __restrict__ dst,
                          const float* __restrict__ eattr, int* __restrict__ cur,
                          int* __restrict__ psrc, uint4* __restrict__ peah) {
    int e = blockIdx.x * blockDim.x + threadIdx.x;
    if (e >= EE) return;
    int d = dst[e];
    int p = atomicAdd(&cur[d], 1);
    psrc[p] = src[e];
    const float4* ea4 = reinterpret_cast<const float4*>(eattr) + (size_t)e * 2;
    peah[p] = pack8h(ea4[0], ea4[1]);
}

__global__ void k_cvt_x(const float* __restrict__ x, __half* __restrict__ xh, int n) {
    int i = blockIdx.x * blockDim.x + threadIdx.x;
    if (i < n) xh[i] = __float2half_rn(x[i]);
}

template<int KIN, int C2>
__global__ void k_cvt_w(const float* __restrict__ wl, const float* __restrict__ wr,
                        __half* __restrict__ wh) {
    int i = blockIdx.x * blockDim.x + threadIdx.x;
    if (i >= KIN * 2 * C2) return;
    int k = i / (2 * C2), c = i % (2 * C2);
    float v = (c < C2) ? wl[k * C2 + c] : wr[k * C2 + (c - C2)];
    wh[i] = __float2half_rn(v);
}

// ---------------- tensor-core transform --------------------------------------
template<int KIN, int COLS, int NPB>
__global__ void k_transform_mma(const __half* __restrict__ xh,
                                const __half* __restrict__ wh,
                                const float* __restrict__ bl, const float* __restrict__ br,
                                __half* __restrict__ xlh, float* __restrict__ xr) {
    constexpr int CG = COLS / 64;
    constexpr int NG = NPB / 16;
    constexpr int WARPS = CG * NG;
    constexpr int THREADS = WARPS * 32;
    constexpr int C2 = COLS / 2;

    __shared__ __half xs[NPB][KIN];
    __shared__ float  os[WARPS][16 * 64];

    int tid = threadIdx.x;
    int warp = tid >> 5, lane = tid & 31;
    size_t nbase = (size_t)blockIdx.x * NPB;

    for (int i = tid; i < NPB * KIN; i += THREADS) {
        int n = i / KIN, k = i % KIN;
        size_t node = nbase + n;
        xs[n][k] = (node < NN) ? xh[node * KIN + k] : __float2half(0.0f);
    }
    __syncthreads();

    int ng = warp / CG, cg = warp % CG;

    wmma::fragment<wmma::accumulator, 16, 16, 16, float> fc[4];
    #pragma unroll
    for (int j = 0; j < 4; j++) wmma::fill_fragment(fc[j], 0.0f);
    wmma::fragment<wmma::matrix_a, 16, 16, 16, __half, wmma::row_major> fa;
    wmma::fragment<wmma::matrix_b, 16, 16, 16, __half, wmma::row_major> fb;

    #pragma unroll
    for (int kk = 0; kk < KIN; kk += 16) {
        wmma::load_matrix_sync(fa, &xs[ng * 16][kk], KIN);
        #pragma unroll
        for (int j = 0; j < 4; j++) {
            wmma::load_matrix_sync(fb, &wh[(size_t)kk * COLS + cg * 64 + j * 16], COLS);
            wmma::mma_sync(fc[j], fa, fb, fc[j]);
        }
    }
    #pragma unroll
    for (int j = 0; j < 4; j++)
        wmma::store_matrix_sync(&os[warp][j * 16], fc[j], 64, wmma::mem_row_major);
    __syncwarp();

    for (int i = lane; i < 16 * 64; i += 32) {
        int r = i / 64, cc = i % 64;
        size_t node = nbase + ng * 16 + r;
        if (node >= NN) continue;
        int col = cg * 64 + cc;
        float v = os[warp][r * 64 + cc];
        if (col < C2) {
            xlh[node * C2 + col] = __float2half_rn(v + bl[col]);
        } else {
            int c2 = col - C2;
            xr[node * C2 + c2] = v + br[c2];
        }
    }
}

// ---------------- CSR GATv2 aggregation, H=4, C=32 (warp per node) ----------
__global__ void __launch_bounds__(256)
k_gat_csr4(const int* __restrict__ off, const int* __restrict__ psrc,
           const uint4* __restrict__ peah,
           const float* __restrict__ we, const float* __restrict__ att,
           const float* __restrict__ bias,
           const __half* __restrict__ xlh, const float* __restrict__ xr,
           __half* __restrict__ hout) {
    int lane = threadIdx.x & 31;
    int node = blockIdx.x * 8 + (threadIdx.x >> 5);
    if (node >= NN) return;

    const float4* we4 = reinterpret_cast<const float4*>(we);
    const uint2*  xl2 = reinterpret_cast<const uint2*>(xlh);

    u64 wxy[8], wzw[8];
    #pragma unroll
    for (int k = 0; k < 8; k++) {
        float4 w = __ldg(&we4[k * 32 + lane]);
        wxy[k] = pk(w.x, w.y); wzw[k] = pk(w.z, w.w);
    }
    float4 at4 = __ldg(&reinterpret_cast<const float4*>(att)[lane]);
    float4 xrv = reinterpret_cast<const float4*>(xr)[(size_t)node * 32 + lane];
    u64 xrxy = pk(xrv.x, xrv.y), xrzw = pk(xrv.z, xrv.w);

    int beg = off[node], end = off[node + 1];
    u64 accxy = pk(0.f, 0.f), acczw = pk(0.f, 0.f);
    float ssum = 0.0f;

    // warm L1 for first chunk's ea line
    asm volatile("prefetch.global.L1 [%0];" :: "l"(&peah[beg]));

    // chunk 0 gather
    int nch = end - beg; if (nch > 8) nch = 8;
    int curS = (lane < nch) ? __ldg(&psrc[beg + lane]) : 0;
    uint2 bufA[8];
    #pragma unroll
    for (int k = 0; k < 8; k++) {
        int s = __shfl_sync(0xffffffffu, curS, k);
        if (k < nch) bufA[k] = __ldg(&xl2[(size_t)s * 32 + lane]);
    }
    int c0 = beg, c1 = beg + 8;
    int nch1 = end - c1; if (nch1 > 8) nch1 = 8;
    int nxtS = (nch1 > 0 && lane < nch1) ? __ldg(&psrc[c1 + lane]) : 0;

    while (true) {
        // gather next chunk + warm its ea line
        uint2 bufB[8];
        if (nch1 > 0) {
            asm volatile("prefetch.global.L1 [%0];" :: "l"(&peah[c1]));
            #pragma unroll
            for (int k = 0; k < 8; k++) {
                int s = __shfl_sync(0xffffffffu, nxtS, k);
                if (k < nch1) bufB[k] = __ldg(&xl2[(size_t)s * 32 + lane]);
            }
        }
        int c2 = c1 + 8;
        int nch2 = end - c2; if (nch2 > 8) nch2 = 8;
        int n2S = (nch2 > 0 && lane < nch2) ? __ldg(&psrc[c2 + lane]) : 0;

        // compute current chunk
        #pragma unroll
        for (int k = 0; k < 8; k++) {
            if (k >= nch) break;
            uint4 ea = __ldg(&peah[c0 + k]);   // uniform, L1-hot
            float2 e01 = __half22float2(u2h(ea.x));
            float2 e23 = __half22float2(u2h(ea.y));
            float2 e45 = __half22float2(u2h(ea.z));
            float2 e67 = __half22float2(u2h(ea.w));
            float2 x01 = __half22float2(u2h(bufA[k].x));
            float2 x23 = __half22float2(u2h(bufA[k].y));
            u64 vxy = pk(x01.x, x01.y), vzw = pk(x23.x, x23.y);

            u64 axy = add2(vxy, xrxy);
            u64 azw = add2(vzw, xrzw);
            u64 s0 = pk(e01.x, e01.x), s1 = pk(e01.y, e01.y);
            u64 s2 = pk(e23.x, e23.x), s3 = pk(e23.y, e23.y);
            u64 s4 = pk(e45.x, e45.x), s5 = pk(e45.y, e45.y);
            u64 s6 = pk(e67.x, e67.x), s7 = pk(e67.y, e67.y);
            axy = fma2(s0, wxy[0], axy); azw = fma2(s0, wzw[0], azw);
            axy = fma2(s1, wxy[1], axy); azw = fma2(s1, wzw[1], azw);
            axy = fma2(s2, wxy[2], axy); azw = fma2(s2, wzw[2], azw);
            axy = fma2(s3, wxy[3], axy); azw = fma2(s3, wzw[3], azw);
            axy = fma2(s4, wxy[4], axy); azw = fma2(s4, wzw[4], azw);
            axy = fma2(s5, wxy[5], axy); azw = fma2(s5, wzw[5], azw);
            axy = fma2(s6, wxy[6], axy); azw = fma2(s6, wzw[6], azw);
            axy = fma2(s7, wxy[7], axy); azw = fma2(s7, wzw[7], azw);
            float2 fxy = upk(axy), fzw = upk(azw);

            float t = lrelu(fxy.x)*at4.x + lrelu(fxy.y)*at4.y
                    + lrelu(fzw.x)*at4.z + lrelu(fzw.y)*at4.w;
            t += __shfl_xor_sync(0xffffffffu, t, 1);
            t += __shfl_xor_sync(0xffffffffu, t, 2);
            t += __shfl_xor_sync(0xffffffffu, t, 4);

            float p = __expf(t);
            ssum += p;
            u64 pp = pk(p, p);
            accxy = fma2(pp, vxy, accxy);
            acczw = fma2(pp, vzw, acczw);
        }

        if (nch1 <= 0) break;
        nch = nch1; c0 = c1;
        #pragma unroll
        for (int k = 0; k < 8; k++) bufA[k] = bufB[k];
        c1 = c2; nch1 = nch2; nxtS = n2S;
    }

    float2 a01 = upk(accxy), a23 = upk(acczw);
    float inv = 1.0f / (ssum + 1e-16f);
    float4 b = __ldg(&reinterpret_cast<const float4*>(bias)[lane]);
    float4 o;
    o.x = eluf(a01.x * inv + b.x);
    o.y = eluf(a01.y * inv + b.y);
    o.z = eluf(a23.x * inv + b.z);
    o.w = eluf(a23.y * inv + b.w);
    uint2 st;
    st.x = h2u(__floats2half2_rn(o.x, o.y));
    st.y = h2u(__floats2half2_rn(o.z, o.w));
    reinterpret_cast<uint2*>(hout)[(size_t)node * 32 + lane] = st;
}

// ---------------- CSR GATv2 aggregation, H=1, C=32 (8 lanes per node) -------
__global__ void __launch_bounds__(256)
k_gat_csr1(const int* __restrict__ off, const int* __restrict__ psrc,
           const uint4* __restrict__ peah,
           const float* __restrict__ we, const float* __restrict__ att,
           const float* __restrict__ bias,
           const __half* __restrict__ xlh, const float* __restrict__ xr,
           float* __restrict__ hout) {
    int lane = threadIdx.x & 31;
    int sub  = lane & 7;
    unsigned gmask = 0xFFu << (lane & 24);
    int node = blockIdx.x * 32 + (threadIdx.x >> 3);
    if (node >= NN) return;

    const float4* we4 = reinterpret_cast<const float4*>(we);
    const uint2*  xl2 = reinterpret_cast<const uint2*>(xlh);

    u64 wxy[8], wzw[8];
    #pragma unroll
    for (int k = 0; k < 8; k++) {
        float4 w = __ldg(&we4[k * 8 + sub]);
        wxy[k] = pk(w.x, w.y); wzw[k] = pk(w.z, w.w);
    }
    float4 at4 = __ldg(&reinterpret_cast<const float4*>(att)[sub]);
    float4 xrv = reinterpret_cast<const float4*>(xr)[(size_t)node * 8 + sub];
    u64 xrxy = pk(xrv.x, xrv.y), xrzw = pk(xrv.z, xrv.w);

    int beg = off[node], end = off[node + 1];
    u64 accxy = pk(0.f, 0.f), acczw = pk(0.f, 0.f);
    float ssum = 0.0f;

    uint4 ea0, ea1;
    uint2 xv0, xv1;
    {
        int s0 = __ldg(&psrc[beg]);
        ea0 = __ldg(&peah[beg]);
        xv0 = __ldg(&xl2[(size_t)s0 * 8 + sub]);
    }
    if (beg + 1 < end) {
        int s1 = __ldg(&psrc[beg + 1]);
        ea1 = __ldg(&peah[beg + 1]);
        xv1 = __ldg(&xl2[(size_t)s1 * 8 + sub]);
    }

    for (int j = beg; j < end; j++) {
        uint4 ea2 = make_uint4(0,0,0,0);
        uint2 xv2 = make_uint2(0,0);
        if (j + 2 < end) {
            int s2 = __ldg(&psrc[j + 2]);
            ea2 = __ldg(&peah[j + 2]);
            xv2 = __ldg(&xl2[(size_t)s2 * 8 + sub]);
        }

        float2 e01 = __half22float2(u2h(ea0.x));
        float2 e23 = __half22float2(u2h(ea0.y));
        float2 e45 = __half22float2(u2h(ea0.z));
        float2 e67 = __half22float2(u2h(ea0.w));
        float2 x01 = __half22float2(u2h(xv0.x));
        float2 x23 = __half22float2(u2h(xv0.y));
        u64 vxy = pk(x01.x, x01.y), vzw = pk(x23.x, x23.y);

        u64 axy = add2(vxy, xrxy);
        u64 azw = add2(vzw, xrzw);
        u64 s0 = pk(e01.x, e01.x), s1 = pk(e01.y, e01.y);
        u64 s2p = pk(e23.x, e23.x), s3 = pk(e23.y, e23.y);
        u64 s4 = pk(e45.x, e45.x), s5 = pk(e45.y, e45.y);
        u64 s6 = pk(e67.x, e67.x), s7 = pk(e67.y, e67.y);
        axy = fma2(s0, wxy[0], axy);  azw = fma2(s0, wzw[0], azw);
        axy = fma2(s1, wxy[1], axy);  azw = fma2(s1, wzw[1], azw);
        axy = fma2(s2p, wxy[2], axy); azw = fma2(s2p, wzw[2], azw);
        axy = fma2(s3, wxy[3], axy);  azw = fma2(s3, wzw[3], azw);
        axy = fma2(s4, wxy[4], axy);  azw = fma2(s4, wzw[4], azw);
        axy = fma2(s5, wxy[5], axy);  azw = fma2(s5, wzw[5], azw);
        axy = fma2(s6, wxy[6], axy);  azw = fma2(s6, wzw[6], azw);
        axy = fma2(s7, wxy[7], axy);  azw = fma2(s7, wzw[7], azw);
        float2 fxy = upk(axy), fzw = upk(azw);

        float t = lrelu(fxy.x)*at4.x + lrelu(fxy.y)*at4.y
                + lrelu(fzw.x)*at4.z + lrelu(fzw.y)*at4.w;
        t += __shfl_xor_sync(gmask, t, 1);
        t += __shfl_xor_sync(gmask, t, 2);
        t += __shfl_xor_sync(gmask, t, 4);

        float p = __expf(t);
        ssum += p;
        u64 pp = pk(p, p);
        accxy = fma2(pp, vxy, accxy);
        acczw = fma2(pp, vzw, acczw);

        ea0 = ea1; xv0 = xv1;
        ea1 = ea2; xv1 = xv2;
    }

    float2 a01 = upk(accxy), a23 = upk(acczw);
    float inv = 1.0f / (ssum + 1e-16f);
    float4 b = __ldg(&reinterpret_cast<const float4*>(bias)[sub]);
    float4 o;
    o.x = eluf(a01.x * inv + b.x);
    o.y = eluf(a01.y * inv + b.y);
    o.z = eluf(a23.x * inv + b.z);
    o.w = eluf(a23.y * inv + b.w);
    reinterpret_cast<float4*>(hout)[(size_t)node * 8 + sub] = o;
}

// ---------------- pooling + MLP head -----------------------------------------
__global__ void k_pool(const float* __restrict__ h, const int* __restrict__ batch,
                       float* __restrict__ gsum, float* __restrict__ gcnt) {
    int idx = blockIdx.x * blockDim.x + threadIdx.x;
    if (idx >= NN * 8) return;
    int n = idx >> 3, c4 = idx & 7;
    int g = batch[n];
    float4 v = reinterpret_cast<const float4*>(h)[idx];
    atomAdd4(reinterpret_cast<float4*>(gsum) + (size_t)g * 8 + c4, v);
    if (c4 == 0) atomicAdd(&gcnt[g], 1.0f);
}

__global__ void k_fc(const float* __restrict__ gsum, const float* __restrict__ gcnt,
                     const float* __restrict__ w1, const float* __restrict__ b1,
                     const float* __restrict__ w2, const float* __restrict__ b2,
                     float* __restrict__ out) {
    int g = threadIdx.x;
    if (g >= GGR) return;
    float inv = 1.0f / fmaxf(gcnt[g], 1.0f);
    float f[HIDC];
    #pragma unroll
    for (int c = 0; c < HIDC; c++) f[c] = gsum[g * HIDC + c] * inv;
    float o[OUTC] = { b2[0], b2[1], b2[2], b2[3] };
    for (int k = 0; k < 2 * HIDC; k++) {
        float h1 = b1[k];
        #pragma unroll
        for (int c = 0; c < HIDC; c++) h1 += f[c] * __ldg(&w1[c * 2 * HIDC + k]);
        h1 = eluf(h1);
        #pragma unroll
        for (int j = 0; j < OUTC; j++) o[j] += h1 * __ldg(&w2[k * OUTC + j]);
    }
    #pragma unroll
    for (int j = 0; j < OUTC; j++) out[g * OUTC + j] = o[j];
}

// ---------------- host launcher ----------------------------------------------
static void fill_f(float* p, float v, size_t n) {
    int n4 = (int)(n / 4);
    k_fill4<<<(n4 + 255) / 256, 256>>>(reinterpret_cast<float4*>(p), v, n4);
}

extern "C" void kernel_launch(void* const* d_in, const int* in_sizes, int n_in,
                              void* d_out, int out_size) {
    const float* x     = (const float*)d_in[0];
    const int*   eidx  = (const int*)  d_in[1];
    const float* eattr = (const float*)d_in[2];
    const int*   batch = (const int*)  d_in[3];
    const float *wl1=(const float*)d_in[4],  *bl1=(const float*)d_in[5];
    const float *wr1=(const float*)d_in[6],  *br1=(const float*)d_in[7];
    const float *we1=(const float*)d_in[8],  *att1=(const float*)d_in[9],  *bc1=(const float*)d_in[10];
    const float *wl2=(const float*)d_in[11], *bl2=(const float*)d_in[12];
    const float *wr2=(const float*)d_in[13], *br2=(const float*)d_in[14];
    const float *we2=(const float*)d_in[15], *att2=(const float*)d_in[16], *bc2=(const float*)d_in[17];
    const float *wl3=(const float*)d_in[18], *bl3=(const float*)d_in[19];
    const float *wr3=(const float*)d_in[20], *br3=(const float*)d_in[21];
    const float *we3=(const float*)d_in[22], *att3=(const float*)d_in[23], *bc3=(const float*)d_in[24];
    const float *w_fc1=(const float*)d_in[25], *b_fc1=(const float*)d_in[26];
    const float *w_fc2=(const float*)d_in[27], *b_fc2=(const float*)d_in[28];

    const int* src = eidx;
    const int* dst = eidx + EE;

    float *xr, *hin, *loop, *gsum, *gcnt;
    __half *xlh, *hinh, *wh1, *wh2, *wh3;
    uint4* peah;
    int *deg, *off, *cur, *psrc;
    cudaGetSymbolAddress((void**)&xlh,  d_xlh);
    cudaGetSymbolAddress((void**)&xr,   d_xr);
    cudaGetSymbolAddress((void**)&hin,  d_hin);
    cudaGetSymbolAddress((void**)&hinh, d_hinh);
    cudaGetSymbolAddress((void**)&loop, d_loop);
    cudaGetSymbolAddress((void**)&deg,  d_deg);
    cudaGetSymbolAddress((void**)&off,  d_off);
    cudaGetSymbolAddress((void**)&cur,  d_cur);
    cudaGetSymbolAddress((void**)&psrc, d_psrc);
    cudaGetSymbolAddress((void**)&peah, d_peah);
    cudaGetSymbolAddress((void**)&wh1,  d_wh1);
    cudaGetSymbolAddress((void**)&wh2,  d_wh2);
    cudaGetSymbolAddress((void**)&wh3,  d_wh3);
    cudaGetSymbolAddress((void**)&gsum, d_gsum);
    cudaGetSymbolAddress((void**)&gcnt, d_gcnt);

    // side stream for overlap (host objects created once, outside capture;
    // device work is identical on every call)
    static cudaStream_t s2 = nullptr;
    static cudaEvent_t evFork = nullptr, evJoin = nullptr;
    if (s2 == nullptr) {
        cudaStreamCreateWithFlags(&s2, cudaStreamNonBlocking);
        cudaEventCreateWithFlags(&evFork, cudaEventDisableTiming);
        cudaEventCreateWithFlags(&evJoin, cudaEventDisableTiming);
    }

    const int AB4 = (NN + 7) / 8;
    const int AB1 = (NN + 31) / 32;

    // ---- fork: fp16 conversions + layer-1 transform on s2 ----
    cudaEventRecord(evFork, 0);
    cudaStreamWaitEvent(s2, evFork, 0);
    k_cvt_x<<<(NN * IN_F + 255) / 256, 256, 0, s2>>>(x, hinh, NN * IN_F);
    k_cvt_w<IN_F, HCC><<<(IN_F * 2 * HCC + 255) / 256, 256, 0, s2>>>(wl1, wr1, wh1);
    k_transform_mma<IN_F, 2 * HCC, 32><<<(NN + 31) / 32, 256, 0, s2>>>(hinh, wh1, bl1, br1, xlh, xr);
    k_cvt_w<HCC, HCC><<<(HCC * 2 * HCC + 255) / 256, 256, 0, s2>>>(wl2, wr2, wh2);
    k_cvt_w<HCC, HIDC><<<(HCC * 2 * HIDC + 255) / 256, 256, 0, s2>>>(wl3, wr3, wh3);

    // ---- main stream: CSR build ----
    fill_f((float*)deg, 0.0f, NN);
    fill_f(loop, 0.0f, (size_t)NN * EDIMC);
    k_hist<<<(EE + 255) / 256, 256>>>(dst, eattr, deg, loop);
    k_loop_div<<<(NN * 2 + 255) / 256, 256>>>(loop, deg);
    k_scan<<<1, 1024>>>(deg, off, cur);
    k_self<<<(NN + 255) / 256, 256>>>(off, loop, psrc, peah);
    k_scatter<<<(EE + 255) / 256, 256>>>(src, dst, eattr, cur, psrc, peah);

    // ---- join ----
    cudaEventRecord(evJoin, s2);
    cudaStreamWaitEvent(0, evJoin, 0);

    // ---- layer 1 agg ----
    k_gat_csr4<<<AB4, 256>>>(off, psrc, peah, we1, att1, bc1, xlh, xr, hinh);

    // ---- layer 2 ----
    k_transform_mma<HCC, 2 * HCC, 32><<<(NN + 31) / 32, 256>>>(hinh, wh2, bl2, br2, xlh, xr);
    k_gat_csr4<<<AB4, 256>>>(off, psrc, peah, we2, att2, bc2, xlh, xr, hinh);

    // ---- layer 3 ----
    k_transform_mma<HCC, 2 * HIDC, 64><<<(NN + 63) / 64, 128>>>(hinh, wh3, bl3, br3, xlh, xr);
    k_gat_csr1<<<AB1, 256>>>(off, psrc, peah, we3, att3, bc3, xlh, xr, hin);

    // ---- pool + MLP ----
    fill_f(gsum, 0.0f, (size_t)GGR * HIDC);
    fill_f(gcnt, 0.0f, GGR);
    k_pool<<<(NN * 8 + 255) / 256, 256>>>(hin, batch, gsum, gcnt);
    k_fc<<<1, 128>>>(gsum, gcnt, w_fc1, b_fc1, w_fc2, b_fc2, (float*)d_out);
}

// round 11
// speedup vs baseline: 1.0000x; 1.0000x over previous
#include <cuda_runtime.h>
#include <cuda_fp16.h>
#include <mma.h>
#include <math.h>

using namespace nvcuda;

#define NN    100000
#define EE    1600000
#define EAT   1700000   // EE + NN self loops
#define GGR   128
#define IN_F  16
#define HIDC  32
#define NHEADS 4
#define EDIMC 8
#define HCC   128
#define OUTC  4

typedef unsigned long long u64;

// ---------------- scratch (device globals: no allocation allowed) ----------
__device__ __half   d_xlh [NN * HCC];
__device__ float    d_xr  [NN * HCC];
__device__ float    d_hin [NN * HCC];
__device__ __half   d_hinh[NN * HCC];
__device__ float    d_loop[NN * EDIMC];
__device__ int      d_deg [NN];
__device__ int      d_off [NN + 1];
__device__ int      d_cur [NN];
__device__ int      d_psrc[EAT];
__device__ uint4    d_peah[EAT];
__device__ __half   d_wh1 [IN_F * 2 * HCC];
__device__ __half   d_wh2 [HCC * 2 * HCC];
__device__ __half   d_wh3 [HCC * 2 * HIDC];
__device__ float    d_gsum[GGR * HIDC];
__device__ float    d_gcnt[GGR];

// ---------------- helpers ---------------------------------------------------
__device__ __forceinline__ void atomAdd4(float4* p, float4 v) { atomicAdd(p, v); }
__device__ __forceinline__ float eluf(float x) { return x > 0.0f ? x : (__expf(x) - 1.0f); }
__device__ __forceinline__ float lrelu(float x) { return x > 0.0f ? x : 0.2f * x; }
__device__ __forceinline__ unsigned h2u(__half2 h) { return *reinterpret_cast<unsigned*>(&h); }
__device__ __forceinline__ __half2  u2h(unsigned u) { return *reinterpret_cast<__half2*>(&u); }

// packed f32x2 helpers (sm_103a dual-rate fp32)
__device__ __forceinline__ u64 pk(float lo, float hi) {
    u64 r; asm("mov.b64 %0, {%1, %2};" : "=l"(r) : "f"(lo), "f"(hi)); return r;
}
__device__ __forceinline__ float2 upk(u64 v) {
    float2 f; asm("mov.b64 {%0, %1}, %2;" : "=f"(f.x), "=f"(f.y) : "l"(v)); return f;
}
__device__ __forceinline__ u64 fma2(u64 a, u64 b, u64 c) {
    u64 r; asm("fma.rn.f32x2 %0, %1, %2, %3;" : "=l"(r) : "l"(a), "l"(b), "l"(c)); return r;
}
__device__ __forceinline__ u64 add2(u64 a, u64 b) {
    u64 r; asm("add.rn.f32x2 %0, %1, %2;" : "=l"(r) : "l"(a), "l"(b)); return r;
}

__device__ __forceinline__ uint4 pack8h(float4 a, float4 b) {
    uint4 o;
    o.x = h2u(__floats2half2_rn(a.x, a.y));
    o.y = h2u(__floats2half2_rn(a.z, a.w));
    o.z = h2u(__floats2half2_rn(b.x, b.y));
    o.w = h2u(__floats2half2_rn(b.z, b.w));
    return o;
}

// ---------------- utility kernels -------------------------------------------
__global__ void k_fill4(float4* __restrict__ p, float v, int n4) {
    int i = blockIdx.x * blockDim.x + threadIdx.x;
    if (i < n4) p[i] = make_float4(v, v, v, v);
}

__global__ void k_hist(const int* __restrict__ dst, const float* __restrict__ eattr,
                       int* __restrict__ deg, float* __restrict__ loop) {
    int e = blockIdx.x * blockDim.x + threadIdx.x;
    if (e >= EE) return;
    int d = dst[e];
    atomicAdd(&deg[d], 1);
    const float4* ea4 = reinterpret_cast<const float4*>(eattr) + (size_t)e * 2;
    float4* l4 = reinterpret_cast<float4*>(loop) + (size_t)d * 2;
    atomAdd4(&l4[0], ea4[0]);
    atomAdd4(&l4[1], ea4[1]);
}

__global__ void k_loop_div(float* __restrict__ loop, const int* __restrict__ deg) {
    int idx = blockIdx.x * blockDim.x + threadIdx.x;
    if (idx >= NN * 2) return;
    int i = idx >> 1;
    float inv = 1.0f / fmaxf((float)deg[i], 1.0f);
    float4* l4 = reinterpret_cast<float4*>(loop);
    float4 v = l4[idx];
    v.x *= inv; v.y *= inv; v.z *= inv; v.w *= inv;
    l4[idx] = v;
}

__global__ void __launch_bounds__(1024)
k_scan(const int* __restrict__ deg, int* __restrict__ off, int* __restrict__ cur) {
    __shared__ int part[1024];
    const int t = threadIdx.x;
    const int CH = (NN + 1023) / 1024;
    int b = t * CH;
    int e2 = b + CH; if (e2 > NN) e2 = NN;
    int s = 0;
    for (int i = b; i < e2; i++) s += deg[i] + 1;
    part[t] = s;
    __syncthreads();
    for (int d = 1; d < 1024; d <<= 1) {
        int v = (t >= d) ? part[t - d] : 0;
        __syncthreads();
        part[t] += v;
        __syncthreads();
    }
    int run = part[t] - s;
    for (int i = b; i < e2; i++) {
        off[i] = run;
        cur[i] = run + 1;
        run += deg[i] + 1;
    }
    if (t == 1023) off[NN] = part[1023];
}

__global__ void k_self(const int* __restrict__ off, const float* __restrict__ loop,
                       int* __restrict__ psrc, uint4* __restrict__ peah) {
    int i = blockIdx.x * blockDim.x + threadIdx.x;
    if (i >= NN) return;
    int p = off[i];
    psrc[p] = i;
    const float4* l4 = reinterpret_cast<const float4*>(loop) + (size_t)i * 2;
    peah[p] = pack8h(l4[0], l4[1]);
}

__global__ void k_scatter(const int* __restrict__ src, const int* __restrict__ dst,
                          const float* __restrict__ eattr, int* __restrict__ cur,
                          int* __restrict__ psrc, uint4* __restrict__ peah) {
    int e = blockIdx.x * blockDim.x + threadIdx.x;
    if (e >= EE) return;
    int d = dst[e];
    int p = atomicAdd(&cur[d], 1);
    psrc[p] = src[e];
    const float4* ea4 = reinterpret_cast<const float4*>(eattr) + (size_t)e * 2;
    peah[p] = pack8h(ea4[0], ea4[1]);
}

__global__ void k_cvt_x(const float* __restrict__ x, __half* __restrict__ xh, int n) {
    int i = blockIdx.x * blockDim.x + threadIdx.x;
    if (i < n) xh[i] = __float2half_rn(x[i]);
}

template<int KIN, int C2>
__global__ void k_cvt_w(const float* __restrict__ wl, const float* __restrict__ wr,
                        __half* __restrict__ wh) {
    int i = blockIdx.x * blockDim.x + threadIdx.x;
    if (i >= KIN * 2 * C2) return;
    int k = i / (2 * C2), c = i % (2 * C2);
    float v = (c < C2) ? wl[k * C2 + c] : wr[k * C2 + (c - C2)];
    wh[i] = __float2half_rn(v);
}

// ---------------- tensor-core transform --------------------------------------
template<int KIN, int COLS, int NPB>
__global__ void k_transform_mma(const __half* __restrict__ xh,
                                const __half* __restrict__ wh,
                                const float* __restrict__ bl, const float* __restrict__ br,
                                __half* __restrict__ xlh, float* __restrict__ xr) {
    constexpr int CG = COLS / 64;
    constexpr int NG = NPB / 16;
    constexpr int WARPS = CG * NG;
    constexpr int THREADS = WARPS * 32;
    constexpr int C2 = COLS / 2;

    __shared__ __half xs[NPB][KIN];
    __shared__ float  os[WARPS][16 * 64];

    int tid = threadIdx.x;
    int warp = tid >> 5, lane = tid & 31;
    size_t nbase = (size_t)blockIdx.x * NPB;

    for (int i = tid; i < NPB * KIN; i += THREADS) {
        int n = i / KIN, k = i % KIN;
        size_t node = nbase + n;
        xs[n][k] = (node < NN) ? xh[node * KIN + k] : __float2half(0.0f);
    }
    __syncthreads();

    int ng = warp / CG, cg = warp % CG;

    wmma::fragment<wmma::accumulator, 16, 16, 16, float> fc[4];
    #pragma unroll
    for (int j = 0; j < 4; j++) wmma::fill_fragment(fc[j], 0.0f);
    wmma::fragment<wmma::matrix_a, 16, 16, 16, __half, wmma::row_major> fa;
    wmma::fragment<wmma::matrix_b, 16, 16, 16, __half, wmma::row_major> fb;

    #pragma unroll
    for (int kk = 0; kk < KIN; kk += 16) {
        wmma::load_matrix_sync(fa, &xs[ng * 16][kk], KIN);
        #pragma unroll
        for (int j = 0; j < 4; j++) {
            wmma::load_matrix_sync(fb, &wh[(size_t)kk * COLS + cg * 64 + j * 16], COLS);
            wmma::mma_sync(fc[j], fa, fb, fc[j]);
        }
    }
    #pragma unroll
    for (int j = 0; j < 4; j++)
        wmma::store_matrix_sync(&os[warp][j * 16], fc[j], 64, wmma::mem_row_major);
    __syncwarp();

    for (int i = lane; i < 16 * 64; i += 32) {
        int r = i / 64, cc = i % 64;
        size_t node = nbase + ng * 16 + r;
        if (node >= NN) continue;
        int col = cg * 64 + cc;
        float v = os[warp][r * 64 + cc];
        if (col < C2) {
            xlh[node * C2 + col] = __float2half_rn(v + bl[col]);
        } else {
            int c2 = col - C2;
            xr[node * C2 + c2] = v + br[c2];
        }
    }
}

// ---------------- CSR GATv2 aggregation, H=4, C=32 (warp per node) ----------
__global__ void __launch_bounds__(256)
k_gat_csr4(const int* __restrict__ off, const int* __restrict__ psrc,
           const uint4* __restrict__ peah,
           const float* __restrict__ we, const float* __restrict__ att,
           const float* __restrict__ bias,
           const __half* __restrict__ xlh, const float* __restrict__ xr,
           __half* __restrict__ hout) {
    int lane = threadIdx.x & 31;
    int node = blockIdx.x * 8 + (threadIdx.x >> 5);
    if (node >= NN) return;

    const float4* we4 = reinterpret_cast<const float4*>(we);
    const uint2*  xl2 = reinterpret_cast<const uint2*>(xlh);

    u64 wxy[8], wzw[8];
    #pragma unroll
    for (int k = 0; k < 8; k++) {
        float4 w = __ldg(&we4[k * 32 + lane]);
        wxy[k] = pk(w.x, w.y); wzw[k] = pk(w.z, w.w);
    }
    float4 at4 = __ldg(&reinterpret_cast<const float4*>(att)[lane]);
    float4 xrv = reinterpret_cast<const float4*>(xr)[(size_t)node * 32 + lane];
    u64 xrxy = pk(xrv.x, xrv.y), xrzw = pk(xrv.z, xrv.w);

    int beg = off[node], end = off[node + 1];
    u64 accxy = pk(0.f, 0.f), acczw = pk(0.f, 0.f);
    float ssum = 0.0f;

    // warm L1 for first chunk's ea line
    asm volatile("prefetch.global.L1 [%0];" :: "l"(&peah[beg]));

    // chunk 0 gather
    int nch = end - beg; if (nch > 8) nch = 8;
    int curS = (lane < nch) ? __ldg(&psrc[beg + lane]) : 0;
    uint2 bufA[8];
    #pragma unroll
    for (int k = 0; k < 8; k++) {
        int s = __shfl_sync(0xffffffffu, curS, k);
        if (k < nch) bufA[k] = __ldg(&xl2[(size_t)s * 32 + lane]);
    }
    int c0 = beg, c1 = beg + 8;
    int nch1 = end - c1; if (nch1 > 8) nch1 = 8;
    int nxtS = (nch1 > 0 && lane < nch1) ? __ldg(&psrc[c1 + lane]) : 0;

    while (true) {
        // gather next chunk + warm its ea line
        uint2 bufB[8];
        if (nch1 > 0) {
            asm volatile("prefetch.global.L1 [%0];" :: "l"(&peah[c1]));
            #pragma unroll
            for (int k = 0; k < 8; k++) {
                int s = __shfl_sync(0xffffffffu, nxtS, k);
                if (k < nch1) bufB[k] = __ldg(&xl2[(size_t)s * 32 + lane]);
            }
        }
        int c2 = c1 + 8;
        int nch2 = end - c2; if (nch2 > 8) nch2 = 8;
        int n2S = (nch2 > 0 && lane < nch2) ? __ldg(&psrc[c2 + lane]) : 0;

        // compute current chunk
        #pragma unroll
        for (int k = 0; k < 8; k++) {
            if (k >= nch) break;
            uint4 ea = __ldg(&peah[c0 + k]);   // uniform, L1-hot
            float2 e01 = __half22float2(u2h(ea.x));
            float2 e23 = __half22float2(u2h(ea.y));
            float2 e45 = __half22float2(u2h(ea.z));
            float2 e67 = __half22float2(u2h(ea.w));
            float2 x01 = __half22float2(u2h(bufA[k].x));
            float2 x23 = __half22float2(u2h(bufA[k].y));
            u64 vxy = pk(x01.x, x01.y), vzw = pk(x23.x, x23.y);

            u64 axy = add2(vxy, xrxy);
            u64 azw = add2(vzw, xrzw);
            u64 s0 = pk(e01.x, e01.x), s1 = pk(e01.y, e01.y);
            u64 s2 = pk(e23.x, e23.x), s3 = pk(e23.y, e23.y);
            u64 s4 = pk(e45.x, e45.x), s5 = pk(e45.y, e45.y);
            u64 s6 = pk(e67.x, e67.x), s7 = pk(e67.y, e67.y);
            axy = fma2(s0, wxy[0], axy); azw = fma2(s0, wzw[0], azw);
            axy = fma2(s1, wxy[1], axy); azw = fma2(s1, wzw[1], azw);
            axy = fma2(s2, wxy[2], axy); azw = fma2(s2, wzw[2], azw);
            axy = fma2(s3, wxy[3], axy); azw = fma2(s3, wzw[3], azw);
            axy = fma2(s4, wxy[4], axy); azw = fma2(s4, wzw[4], azw);
            axy = fma2(s5, wxy[5], axy); azw = fma2(s5, wzw[5], azw);
            axy = fma2(s6, wxy[6], axy); azw = fma2(s6, wzw[6], azw);
            axy = fma2(s7, wxy[7], axy); azw = fma2(s7, wzw[7], azw);
            float2 fxy = upk(axy), fzw = upk(azw);

            float t = lrelu(fxy.x)*at4.x + lrelu(fxy.y)*at4.y
                    + lrelu(fzw.x)*at4.z + lrelu(fzw.y)*at4.w;
            t += __shfl_xor_sync(0xffffffffu, t, 1);
            t += __shfl_xor_sync(0xffffffffu, t, 2);
            t += __shfl_xor_sync(0xffffffffu, t, 4);

            float p = __expf(t);
            ssum += p;
            u64 pp = pk(p, p);
            accxy = fma2(pp, vxy, accxy);
            acczw = fma2(pp, vzw, acczw);
        }

        if (nch1 <= 0) break;
        nch = nch1; c0 = c1;
        #pragma unroll
        for (int k = 0; k < 8; k++) bufA[k] = bufB[k];
        c1 = c2; nch1 = nch2; nxtS = n2S;
    }

    float2 a01 = upk(accxy), a23 = upk(acczw);
    float inv = 1.0f / (ssum + 1e-16f);
    float4 b = __ldg(&reinterpret_cast<const float4*>(bias)[lane]);
    float4 o;
    o.x = eluf(a01.x * inv + b.x);
    o.y = eluf(a01.y * inv + b.y);
    o.z = eluf(a23.x * inv + b.z);
    o.w = eluf(a23.y * inv + b.w);
    uint2 st;
    st.x = h2u(__floats2half2_rn(o.x, o.y));
    st.y = h2u(__floats2half2_rn(o.z, o.w));
    reinterpret_cast<uint2*>(hout)[(size_t)node * 32 + lane] = st;
}

// ---------------- CSR GATv2 aggregation, H=1, C=32 (8 lanes per node) -------
__global__ void __launch_bounds__(256)
k_gat_csr1(const int* __restrict__ off, const int* __restrict__ psrc,
           const uint4* __restrict__ peah,
           const float* __restrict__ we, const float* __restrict__ att,
           const float* __restrict__ bias,
           const __half* __restrict__ xlh, const float* __restrict__ xr,
           float* __restrict__ hout) {
    int lane = threadIdx.x & 31;
    int sub  = lane & 7;
    unsigned gmask = 0xFFu << (lane & 24);
    int node = blockIdx.x * 32 + (threadIdx.x >> 3);
    if (node >= NN) return;

    const float4* we4 = reinterpret_cast<const float4*>(we);
    const uint2*  xl2 = reinterpret_cast<const uint2*>(xlh);

    u64 wxy[8], wzw[8];
    #pragma unroll
    for (int k = 0; k < 8; k++) {
        float4 w = __ldg(&we4[k * 8 + sub]);
        wxy[k] = pk(w.x, w.y); wzw[k] = pk(w.z, w.w);
    }
    float4 at4 = __ldg(&reinterpret_cast<const float4*>(att)[sub]);
    float4 xrv = reinterpret_cast<const float4*>(xr)[(size_t)node * 8 + sub];
    u64 xrxy = pk(xrv.x, xrv.y), xrzw = pk(xrv.z, xrv.w);

    int beg = off[node], end = off[node + 1];
    u64 accxy = pk(0.f, 0.f), acczw = pk(0.f, 0.f);
    float ssum = 0.0f;

    uint4 ea0, ea1;
    uint2 xv0, xv1;
    {
        int s0 = __ldg(&psrc[beg]);
        ea0 = __ldg(&peah[beg]);
        xv0 = __ldg(&xl2[(size_t)s0 * 8 + sub]);
    }
    if (beg + 1 < end) {
        int s1 = __ldg(&psrc[beg + 1]);
        ea1 = __ldg(&peah[beg + 1]);
        xv1 = __ldg(&xl2[(size_t)s1 * 8 + sub]);
    }

    for (int j = beg; j < end; j++) {
        uint4 ea2 = make_uint4(0,0,0,0);
        uint2 xv2 = make_uint2(0,0);
        if (j + 2 < end) {
            int s2 = __ldg(&psrc[j + 2]);
            ea2 = __ldg(&peah[j + 2]);
            xv2 = __ldg(&xl2[(size_t)s2 * 8 + sub]);
        }

        float2 e01 = __half22float2(u2h(ea0.x));
        float2 e23 = __half22float2(u2h(ea0.y));
        float2 e45 = __half22float2(u2h(ea0.z));
        float2 e67 = __half22float2(u2h(ea0.w));
        float2 x01 = __half22float2(u2h(xv0.x));
        float2 x23 = __half22float2(u2h(xv0.y));
        u64 vxy = pk(x01.x, x01.y), vzw = pk(x23.x, x23.y);

        u64 axy = add2(vxy, xrxy);
        u64 azw = add2(vzw, xrzw);
        u64 s0 = pk(e01.x, e01.x), s1 = pk(e01.y, e01.y);
        u64 s2p = pk(e23.x, e23.x), s3 = pk(e23.y, e23.y);
        u64 s4 = pk(e45.x, e45.x), s5 = pk(e45.y, e45.y);
        u64 s6 = pk(e67.x, e67.x), s7 = pk(e67.y, e67.y);
        axy = fma2(s0, wxy[0], axy);  azw = fma2(s0, wzw[0], azw);
        axy = fma2(s1, wxy[1], axy);  azw = fma2(s1, wzw[1], azw);
        axy = fma2(s2p, wxy[2], axy); azw = fma2(s2p, wzw[2], azw);
        axy = fma2(s3, wxy[3], axy);  azw = fma2(s3, wzw[3], azw);
        axy = fma2(s4, wxy[4], axy);  azw = fma2(s4, wzw[4], azw);
        axy = fma2(s5, wxy[5], axy);  azw = fma2(s5, wzw[5], azw);
        axy = fma2(s6, wxy[6], axy);  azw = fma2(s6, wzw[6], azw);
        axy = fma2(s7, wxy[7], axy);  azw = fma2(s7, wzw[7], azw);
        float2 fxy = upk(axy), fzw = upk(azw);

        float t = lrelu(fxy.x)*at4.x + lrelu(fxy.y)*at4.y
                + lrelu(fzw.x)*at4.z + lrelu(fzw.y)*at4.w;
        t += __shfl_xor_sync(gmask, t, 1);
        t += __shfl_xor_sync(gmask, t, 2);
        t += __shfl_xor_sync(gmask, t, 4);

        float p = __expf(t);
        ssum += p;
        u64 pp = pk(p, p);
        accxy = fma2(pp, vxy, accxy);
        acczw = fma2(pp, vzw, acczw);

        ea0 = ea1; xv0 = xv1;
        ea1 = ea2; xv1 = xv2;
    }

    float2 a01 = upk(accxy), a23 = upk(acczw);
    float inv = 1.0f / (ssum + 1e-16f);
    float4 b = __ldg(&reinterpret_cast<const float4*>(bias)[sub]);
    float4 o;
    o.x = eluf(a01.x * inv + b.x);
    o.y = eluf(a01.y * inv + b.y);
    o.z = eluf(a23.x * inv + b.z);
    o.w = eluf(a23.y * inv + b.w);
    reinterpret_cast<float4*>(hout)[(size_t)node * 8 + sub] = o;
}

// ---------------- pooling + MLP head -----------------------------------------
__global__ void k_pool(const float* __restrict__ h, const int* __restrict__ batch,
                       float* __restrict__ gsum, float* __restrict__ gcnt) {
    int idx = blockIdx.x * blockDim.x + threadIdx.x;
    if (idx >= NN * 8) return;
    int n = idx >> 3, c4 = idx & 7;
    int g = batch[n];
    float4 v = reinterpret_cast<const float4*>(h)[idx];
    atomAdd4(reinterpret_cast<float4*>(gsum) + (size_t)g * 8 + c4, v);
    if (c4 == 0) atomicAdd(&gcnt[g], 1.0f);
}

__global__ void k_fc(const float* __restrict__ gsum, const float* __restrict__ gcnt,
                     const float* __restrict__ w1, const float* __restrict__ b1,
                     const float* __restrict__ w2, const float* __restrict__ b2,
                     float* __restrict__ out) {
    int g = threadIdx.x;
    if (g >= GGR) return;
    float inv = 1.0f / fmaxf(gcnt[g], 1.0f);
    float f[HIDC];
    #pragma unroll
    for (int c = 0; c < HIDC; c++) f[c] = gsum[g * HIDC + c] * inv;
    float o[OUTC] = { b2[0], b2[1], b2[2], b2[3] };
    for (int k = 0; k < 2 * HIDC; k++) {
        float h1 = b1[k];
        #pragma unroll
        for (int c = 0; c < HIDC; c++) h1 += f[c] * __ldg(&w1[c * 2 * HIDC + k]);
        h1 = eluf(h1);
        #pragma unroll
        for (int j = 0; j < OUTC; j++) o[j] += h1 * __ldg(&w2[k * OUTC + j]);
    }
    #pragma unroll
    for (int j = 0; j < OUTC; j++) out[g * OUTC + j] = o[j];
}

// ---------------- host launcher ----------------------------------------------
static void fill_f(float* p, float v, size_t n) {
    int n4 = (int)(n / 4);
    k_fill4<<<(n4 + 255) / 256, 256>>>(reinterpret_cast<float4*>(p), v, n4);
}

extern "C" void kernel_launch(void* const* d_in, const int* in_sizes, int n_in,
                              void* d_out, int out_size) {
    const float* x     = (const float*)d_in[0];
    const int*   eidx  = (const int*)  d_in[1];
    const float* eattr = (const float*)d_in[2];
    const int*   batch = (const int*)  d_in[3];
    const float *wl1=(const float*)d_in[4],  *bl1=(const float*)d_in[5];
    const float *wr1=(const float*)d_in[6],  *br1=(const float*)d_in[7];
    const float *we1=(const float*)d_in[8],  *att1=(const float*)d_in[9],  *bc1=(const float*)d_in[10];
    const float *wl2=(const float*)d_in[11], *bl2=(const float*)d_in[12];
    const float *wr2=(const float*)d_in[13], *br2=(const float*)d_in[14];
    const float *we2=(const float*)d_in[15], *att2=(const float*)d_in[16], *bc2=(const float*)d_in[17];
    const float *wl3=(const float*)d_in[18], *bl3=(const float*)d_in[19];
    const float *wr3=(const float*)d_in[20], *br3=(const float*)d_in[21];
    const float *we3=(const float*)d_in[22], *att3=(const float*)d_in[23], *bc3=(const float*)d_in[24];
    const float *w_fc1=(const float*)d_in[25], *b_fc1=(const float*)d_in[26];
    const float *w_fc2=(const float*)d_in[27], *b_fc2=(const float*)d_in[28];

    const int* src = eidx;
    const int* dst = eidx + EE;

    float *xr, *hin, *loop, *gsum, *gcnt;
    __half *xlh, *hinh, *wh1, *wh2, *wh3;
    uint4* peah;
    int *deg, *off, *cur, *psrc;
    cudaGetSymbolAddress((void**)&xlh,  d_xlh);
    cudaGetSymbolAddress((void**)&xr,   d_xr);
    cudaGetSymbolAddress((void**)&hin,  d_hin);
    cudaGetSymbolAddress((void**)&hinh, d_hinh);
    cudaGetSymbolAddress((void**)&loop, d_loop);
    cudaGetSymbolAddress((void**)&deg,  d_deg);
    cudaGetSymbolAddress((void**)&off,  d_off);
    cudaGetSymbolAddress((void**)&cur,  d_cur);
    cudaGetSymbolAddress((void**)&psrc, d_psrc);
    cudaGetSymbolAddress((void**)&peah, d_peah);
    cudaGetSymbolAddress((void**)&wh1,  d_wh1);
    cudaGetSymbolAddress((void**)&wh2,  d_wh2);
    cudaGetSymbolAddress((void**)&wh3,  d_wh3);
    cudaGetSymbolAddress((void**)&gsum, d_gsum);
    cudaGetSymbolAddress((void**)&gcnt, d_gcnt);

    // side stream for overlap (host objects created once, outside capture;
    // device work is identical on every call)
    static cudaStream_t s2 = nullptr;
    static cudaEvent_t evFork = nullptr, evJoin = nullptr;
    if (s2 == nullptr) {
        cudaStreamCreateWithFlags(&s2, cudaStreamNonBlocking);
        cudaEventCreateWithFlags(&evFork, cudaEventDisableTiming);
        cudaEventCreateWithFlags(&evJoin, cudaEventDisableTiming);
    }

    const int AB4 = (NN + 7) / 8;
    const int AB1 = (NN + 31) / 32;

    // ---- fork: fp16 conversions + layer-1 transform on s2 ----
    cudaEventRecord(evFork, 0);
    cudaStreamWaitEvent(s2, evFork, 0);
    k_cvt_x<<<(NN * IN_F + 255) / 256, 256, 0, s2>>>(x, hinh, NN * IN_F);
    k_cvt_w<IN_F, HCC><<<(IN_F * 2 * HCC + 255) / 256, 256, 0, s2>>>(wl1, wr1, wh1);
    k_transform_mma<IN_F, 2 * HCC, 32><<<(NN + 31) / 32, 256, 0, s2>>>(hinh, wh1, bl1, br1, xlh, xr);
    k_cvt_w<HCC, HCC><<<(HCC * 2 * HCC + 255) / 256, 256, 0, s2>>>(wl2, wr2, wh2);
    k_cvt_w<HCC, HIDC><<<(HCC * 2 * HIDC + 255) / 256, 256, 0, s2>>>(wl3, wr3, wh3);

    // ---- main stream: CSR build ----
    fill_f((float*)deg, 0.0f, NN);
    fill_f(loop, 0.0f, (size_t)NN * EDIMC);
    k_hist<<<(EE + 255) / 256, 256>>>(dst, eattr, deg, loop);
    k_loop_div<<<(NN * 2 + 255) / 256, 256>>>(loop, deg);
    k_scan<<<1, 1024>>>(deg, off, cur);
    k_self<<<(NN + 255) / 256, 256>>>(off, loop, psrc, peah);
    k_scatter<<<(EE + 255) / 256, 256>>>(src, dst, eattr, cur, psrc, peah);

    // ---- join ----
    cudaEventRecord(evJoin, s2);
    cudaStreamWaitEvent(0, evJoin, 0);

    // ---- layer 1 agg ----
    k_gat_csr4<<<AB4, 256>>>(off, psrc, peah, we1, att1, bc1, xlh, xr, hinh);

    // ---- layer 2 ----
    k_transform_mma<HCC, 2 * HCC, 32><<<(NN + 31) / 32, 256>>>(hinh, wh2, bl2, br2, xlh, xr);
    k_gat_csr4<<<AB4, 256>>>(off, psrc, peah, we2, att2, bc2, xlh, xr, hinh);

    // ---- layer 3 ----
    k_transform_mma<HCC, 2 * HIDC, 64><<<(NN + 63) / 64, 128>>>(hinh, wh3, bl3, br3, xlh, xr);
    k_gat_csr1<<<AB1, 256>>>(off, psrc, peah, we3, att3, bc3, xlh, xr, hin);

    // ---- pool + MLP ----
    fill_f(gsum, 0.0f, (size_t)GGR * HIDC);
    fill_f(gcnt, 0.0f, GGR);
    k_pool<<<(NN * 8 + 255) / 256, 256>>>(hin, batch, gsum, gcnt);
    k_fc<<<1, 128>>>(gsum, gcnt, w_fc1, b_fc1, w_fc2, b_fc2, (float*)d_out);
}

// round 12
// speedup vs baseline: 1.1358x; 1.1357x over previous
#include <cuda_runtime.h>
#include <cuda_fp16.h>
#include <mma.h>
#include <math.h>

using namespace nvcuda;

#define NN    100000
#define EE    1600000
#define EAT   1700000   // EE + NN self loops
#define GGR   128
#define IN_F  16
#define HIDC  32
#define NHEADS 4
#define EDIMC 8
#define HCC   128
#define OUTC  4

// ---------------- scratch (device globals: no allocation allowed) ----------
__device__ __half   d_xlh [NN * HCC];
__device__ float    d_xr  [NN * HCC];
__device__ __half   d_hinh[NN * HCC];
__device__ float    d_loop[NN * EDIMC];
__device__ int      d_deg [NN];
__device__ int      d_off [NN + 1];
__device__ int      d_cur [NN];
__device__ int      d_psrc[EAT];
__device__ uint4    d_peah[EAT];
__device__ __half   d_wh1 [IN_F * 2 * HCC];
__device__ __half   d_wh2 [HCC * 2 * HCC];
__device__ __half   d_wh3 [HCC * 2 * HIDC];
__device__ float    d_gsum[GGR * HIDC];
__device__ float    d_gcnt[GGR];

// ---------------- helpers ---------------------------------------------------
__device__ __forceinline__ void atomAdd4(float4* p, float4 v) { atomicAdd(p, v); }
__device__ __forceinline__ float eluf(float x) { return x > 0.0f ? x : (__expf(x) - 1.0f); }
__device__ __forceinline__ float lrelu(float x) { return x > 0.0f ? x : 0.2f * x; }
__device__ __forceinline__ unsigned h2u(__half2 h) { return *reinterpret_cast<unsigned*>(&h); }
__device__ __forceinline__ __half2  u2h(unsigned u) { return *reinterpret_cast<__half2*>(&u); }

__device__ __forceinline__ uint4 pack8h(float4 a, float4 b) {
    uint4 o;
    o.x = h2u(__floats2half2_rn(a.x, a.y));
    o.y = h2u(__floats2half2_rn(a.z, a.w));
    o.z = h2u(__floats2half2_rn(b.x, b.y));
    o.w = h2u(__floats2half2_rn(b.z, b.w));
    return o;
}

// ---------------- utility kernels -------------------------------------------
__global__ void k_fill4(float4* __restrict__ p, float v, int n4) {
    int i = blockIdx.x * blockDim.x + threadIdx.x;
    if (i < n4) p[i] = make_float4(v, v, v, v);
}

__global__ void k_hist(const int* __restrict__ dst, const float* __restrict__ eattr,
                       int* __restrict__ deg, float* __restrict__ loop) {
    int e = blockIdx.x * blockDim.x + threadIdx.x;
    if (e >= EE) return;
    int d = dst[e];
    atomicAdd(&deg[d], 1);
    const float4* ea4 = reinterpret_cast<const float4*>(eattr) + (size_t)e * 2;
    float4* l4 = reinterpret_cast<float4*>(loop) + (size_t)d * 2;
    atomAdd4(&l4[0], ea4[0]);
    atomAdd4(&l4[1], ea4[1]);
}

__global__ void k_loop_div(float* __restrict__ loop, const int* __restrict__ deg) {
    int idx = blockIdx.x * blockDim.x + threadIdx.x;
    if (idx >= NN * 2) return;
    int i = idx >> 1;
    float inv = 1.0f / fmaxf((float)deg[i], 1.0f);
    float4* l4 = reinterpret_cast<float4*>(loop);
    float4 v = l4[idx];
    v.x *= inv; v.y *= inv; v.z *= inv; v.w *= inv;
    l4[idx] = v;
}

__global__ void __launch_bounds__(1024)
k_scan(const int* __restrict__ deg, int* __restrict__ off, int* __restrict__ cur) {
    __shared__ int part[1024];
    const int t = threadIdx.x;
    const int CH = (NN + 1023) / 1024;
    int b = t * CH;
    int e2 = b + CH; if (e2 > NN) e2 = NN;
    int s = 0;
    for (int i = b; i < e2; i++) s += deg[i] + 1;
    part[t] = s;
    __syncthreads();
    for (int d = 1; d < 1024; d <<= 1) {
        int v = (t >= d) ? part[t - d] : 0;
        __syncthreads();
        part[t] += v;
        __syncthreads();
    }
    int run = part[t] - s;
    for (int i = b; i < e2; i++) {
        off[i] = run;
        cur[i] = run + 1;
        run += deg[i] + 1;
    }
    if (t == 1023) off[NN] = part[1023];
}

__global__ void k_self(const int* __restrict__ off, const float* __restrict__ loop,
                       int* __restrict__ psrc, uint4* __restrict__ peah) {
    int i = blockIdx.x * blockDim.x + threadIdx.x;
    if (i >= NN) return;
    int p = off[i];
    psrc[p] = i;
    const float4* l4 = reinterpret_cast<const float4*>(loop) + (size_t)i * 2;
    peah[p] = pack8h(l4[0], l4[1]);
}

__global__ void k_scatter(const int* __restrict__ src, const int* __restrict__ dst,
                          const float* __restrict__ eattr, int* __restrict__ cur,
                          int* __restrict__ psrc, uint4* __restrict__ peah) {
    int e = blockIdx.x * blockDim.x + threadIdx.x;
    if (e >= EE) return;
    int d = dst[e];
    int p = atomicAdd(&cur[d], 1);
    psrc[p] = src[e];
    const float4* ea4 = reinterpret_cast<const float4*>(eattr) + (size_t)e * 2;
    peah[p] = pack8h(ea4[0], ea4[1]);
}

template<int KIN, int C2>
__global__ void k_cvt_w(const float* __restrict__ wl, const float* __restrict__ wr,
                        __half* __restrict__ wh) {
    int i = blockIdx.x * blockDim.x + threadIdx.x;
    if (i >= KIN * 2 * C2) return;
    int k = i / (2 * C2), c = i % (2 * C2);
    float v = (c < C2) ? wl[k * C2 + c] : wr[k * C2 + (c - C2)];
    wh[i] = __float2half_rn(v);
}

// ---------------- tensor-core transform --------------------------------------
// IS_F32: input activations are fp32 (converted while staging into smem)
template<int KIN, int COLS, int NPB, bool IS_F32>
__global__ void k_transform_mma(const void* __restrict__ xin,
                                const __half* __restrict__ wh,
                                const float* __restrict__ bl, const float* __restrict__ br,
                                __half* __restrict__ xlh, float* __restrict__ xr) {
    constexpr int CG = COLS / 64;
    constexpr int NG = NPB / 16;
    constexpr int WARPS = CG * NG;
    constexpr int THREADS = WARPS * 32;
    constexpr int C2 = COLS / 2;

    __shared__ __half xs[NPB][KIN];
    __shared__ float  os[WARPS][16 * 64];

    int tid = threadIdx.x;
    int warp = tid >> 5, lane = tid & 31;
    size_t nbase = (size_t)blockIdx.x * NPB;

    for (int i = tid; i < NPB * KIN; i += THREADS) {
        int n = i / KIN, k = i % KIN;
        size_t node = nbase + n;
        __half v = __float2half(0.0f);
        if (node < NN) {
            if constexpr (IS_F32)
                v = __float2half_rn(reinterpret_cast<const float*>(xin)[node * KIN + k]);
            else
                v = reinterpret_cast<const __half*>(xin)[node * KIN + k];
        }
        xs[n][k] = v;
    }
    __syncthreads();

    int ng = warp / CG, cg = warp % CG;

    wmma::fragment<wmma::accumulator, 16, 16, 16, float> fc[4];
    #pragma unroll
    for (int j = 0; j < 4; j++) wmma::fill_fragment(fc[j], 0.0f);
    wmma::fragment<wmma::matrix_a, 16, 16, 16, __half, wmma::row_major> fa;
    wmma::fragment<wmma::matrix_b, 16, 16, 16, __half, wmma::row_major> fb;

    #pragma unroll
    for (int kk = 0; kk < KIN; kk += 16) {
        wmma::load_matrix_sync(fa, &xs[ng * 16][kk], KIN);
        #pragma unroll
        for (int j = 0; j < 4; j++) {
            wmma::load_matrix_sync(fb, &wh[(size_t)kk * COLS + cg * 64 + j * 16], COLS);
            wmma::mma_sync(fc[j], fa, fb, fc[j]);
        }
    }
    #pragma unroll
    for (int j = 0; j < 4; j++)
        wmma::store_matrix_sync(&os[warp][j * 16], fc[j], 64, wmma::mem_row_major);
    __syncwarp();

    for (int i = lane; i < 16 * 64; i += 32) {
        int r = i / 64, cc = i % 64;
        size_t node = nbase + ng * 16 + r;
        if (node >= NN) continue;
        int col = cg * 64 + cc;
        float v = os[warp][r * 64 + cc];
        if (col < C2) {
            xlh[node * C2 + col] = __float2half_rn(v + bl[col]);
        } else {
            int c2 = col - C2;
            xr[node * C2 + c2] = v + br[c2];
        }
    }
}

// ---------------- CSR GATv2 aggregation, H=4, C=32 (warp per node) ----------
// Chunked batch gathers (MLP=8) + double buffering; writes fp16 output.
__global__ void __launch_bounds__(256)
k_gat_csr4(const int* __restrict__ off, const int* __restrict__ psrc,
           const uint4* __restrict__ peah,
           const float* __restrict__ we, const float* __restrict__ att,
           const float* __restrict__ bias,
           const __half* __restrict__ xlh, const float* __restrict__ xr,
           __half* __restrict__ hout) {
    int lane = threadIdx.x & 31;
    int node = blockIdx.x * 8 + (threadIdx.x >> 5);
    if (node >= NN) return;

    const float4* we4 = reinterpret_cast<const float4*>(we);
    const uint2*  xl2 = reinterpret_cast<const uint2*>(xlh);

    float4 w4[8];
    #pragma unroll
    for (int k = 0; k < 8; k++) w4[k] = __ldg(&we4[k * 32 + lane]);
    float4 at4 = __ldg(&reinterpret_cast<const float4*>(att)[lane]);
    float4 xrv = reinterpret_cast<const float4*>(xr)[(size_t)node * 32 + lane];

    int beg = off[node], end = off[node + 1];
    float4 acc = make_float4(0.f, 0.f, 0.f, 0.f);
    float ssum = 0.0f;

    // chunk 0 meta + gather
    int nch = end - beg; if (nch > 8) nch = 8;
    int curS = 0; uint4 curE = make_uint4(0, 0, 0, 0);
    if (lane < nch) { curS = __ldg(&psrc[beg + lane]); curE = __ldg(&peah[beg + lane]); }
    uint2 bufA[8];
    #pragma unroll
    for (int k = 0; k < 8; k++) {
        int s = __shfl_sync(0xffffffffu, curS, k);
        if (k < nch) bufA[k] = __ldg(&xl2[(size_t)s * 32 + lane]);
    }
    // chunk 1 meta
    int c1 = beg + 8;
    int nch1 = end - c1; if (nch1 > 8) nch1 = 8;
    int nxtS = 0; uint4 nxtE = make_uint4(0, 0, 0, 0);
    if (nch1 > 0 && lane < nch1) { nxtS = __ldg(&psrc[c1 + lane]); nxtE = __ldg(&peah[c1 + lane]); }

    while (true) {
        // gather next chunk (overlaps current compute)
        uint2 bufB[8];
        if (nch1 > 0) {
            #pragma unroll
            for (int k = 0; k < 8; k++) {
                int s = __shfl_sync(0xffffffffu, nxtS, k);
                if (k < nch1) bufB[k] = __ldg(&xl2[(size_t)s * 32 + lane]);
            }
        }
        // prefetch chunk+2 meta
        int c2 = c1 + 8;
        int nch2 = end - c2; if (nch2 > 8) nch2 = 8;
        int n2S = 0; uint4 n2E = make_uint4(0, 0, 0, 0);
        if (nch2 > 0 && lane < nch2) { n2S = __ldg(&psrc[c2 + lane]); n2E = __ldg(&peah[c2 + lane]); }

        // compute current chunk
        #pragma unroll
        for (int k = 0; k < 8; k++) {
            if (k >= nch) break;
            unsigned ue0 = __shfl_sync(0xffffffffu, curE.x, k);
            unsigned ue1 = __shfl_sync(0xffffffffu, curE.y, k);
            unsigned ue2 = __shfl_sync(0xffffffffu, curE.z, k);
            unsigned ue3 = __shfl_sync(0xffffffffu, curE.w, k);
            float2 e01 = __half22float2(u2h(ue0));
            float2 e23 = __half22float2(u2h(ue1));
            float2 e45 = __half22float2(u2h(ue2));
            float2 e67 = __half22float2(u2h(ue3));
            float2 x01 = __half22float2(u2h(bufA[k].x));
            float2 x23 = __half22float2(u2h(bufA[k].y));
            float4 xv = make_float4(x01.x, x01.y, x23.x, x23.y);

            float4 a = make_float4(xv.x + xrv.x, xv.y + xrv.y, xv.z + xrv.z, xv.w + xrv.w);
            a.x += e01.x*w4[0].x + e01.y*w4[1].x + e23.x*w4[2].x + e23.y*w4[3].x
                 + e45.x*w4[4].x + e45.y*w4[5].x + e67.x*w4[6].x + e67.y*w4[7].x;
            a.y += e01.x*w4[0].y + e01.y*w4[1].y + e23.x*w4[2].y + e23.y*w4[3].y
                 + e45.x*w4[4].y + e45.y*w4[5].y + e67.x*w4[6].y + e67.y*w4[7].y;
            a.z += e01.x*w4[0].z + e01.y*w4[1].z + e23.x*w4[2].z + e23.y*w4[3].z
                 + e45.x*w4[4].z + e45.y*w4[5].z + e67.x*w4[6].z + e67.y*w4[7].z;
            a.w += e01.x*w4[0].w + e01.y*w4[1].w + e23.x*w4[2].w + e23.y*w4[3].w
                 + e45.x*w4[4].w + e45.y*w4[5].w + e67.x*w4[6].w + e67.y*w4[7].w;

            float t = lrelu(a.x)*at4.x + lrelu(a.y)*at4.y
                    + lrelu(a.z)*at4.z + lrelu(a.w)*at4.w;
            t += __shfl_xor_sync(0xffffffffu, t, 1);
            t += __shfl_xor_sync(0xffffffffu, t, 2);
            t += __shfl_xor_sync(0xffffffffu, t, 4);

            float p = __expf(t);
            ssum += p;
            acc.x += p * xv.x; acc.y += p * xv.y;
            acc.z += p * xv.z; acc.w += p * xv.w;
        }

        if (nch1 <= 0) break;
        nch = nch1; curE = nxtE;
        #pragma unroll
        for (int k = 0; k < 8; k++) bufA[k] = bufB[k];
        c1 = c2; nch1 = nch2; nxtS = n2S; nxtE = n2E;
    }

    float inv = 1.0f / (ssum + 1e-16f);
    float4 b = __ldg(&reinterpret_cast<const float4*>(bias)[lane]);
    float4 o;
    o.x = eluf(acc.x * inv + b.x);
    o.y = eluf(acc.y * inv + b.y);
    o.z = eluf(acc.z * inv + b.z);
    o.w = eluf(acc.w * inv + b.w);
    uint2 st;
    st.x = h2u(__floats2half2_rn(o.x, o.y));
    st.y = h2u(__floats2half2_rn(o.z, o.w));
    reinterpret_cast<uint2*>(hout)[(size_t)node * 32 + lane] = st;
}

// ---------------- CSR GATv2 aggregation, H=1, C=32, fused mean-pool ---------
__global__ void __launch_bounds__(256)
k_gat_csr1_pool(const int* __restrict__ off, const int* __restrict__ psrc,
                const uint4* __restrict__ peah,
                const float* __restrict__ we, const float* __restrict__ att,
                const float* __restrict__ bias, const int* __restrict__ batch,
                const __half* __restrict__ xlh, const float* __restrict__ xr,
                float* __restrict__ gsum, float* __restrict__ gcnt) {
    int lane = threadIdx.x & 31;
    int sub  = lane & 7;
    unsigned gmask = 0xFFu << (lane & 24);
    int node = blockIdx.x * 32 + (threadIdx.x >> 3);
    if (node >= NN) return;

    const float4* we4 = reinterpret_cast<const float4*>(we);
    const uint2*  xl2 = reinterpret_cast<const uint2*>(xlh);

    float4 w4[8];
    #pragma unroll
    for (int k = 0; k < 8; k++) w4[k] = __ldg(&we4[k * 8 + sub]);
    float4 at4 = __ldg(&reinterpret_cast<const float4*>(att)[sub]);
    float4 xrv = reinterpret_cast<const float4*>(xr)[(size_t)node * 8 + sub];

    int beg = off[node], end = off[node + 1];
    float4 acc = make_float4(0.f, 0.f, 0.f, 0.f);
    float ssum = 0.0f;

    uint4 ea0, ea1;
    uint2 xv0, xv1;
    {
        int s0 = __ldg(&psrc[beg]);
        ea0 = __ldg(&peah[beg]);
        xv0 = __ldg(&xl2[(size_t)s0 * 8 + sub]);
    }
    if (beg + 1 < end) {
        int s1 = __ldg(&psrc[beg + 1]);
        ea1 = __ldg(&peah[beg + 1]);
        xv1 = __ldg(&xl2[(size_t)s1 * 8 + sub]);
    }

    for (int j = beg; j < end; j++) {
        uint4 ea2 = make_uint4(0,0,0,0);
        uint2 xv2 = make_uint2(0,0);
        if (j + 2 < end) {
            int s2 = __ldg(&psrc[j + 2]);
            ea2 = __ldg(&peah[j + 2]);
            xv2 = __ldg(&xl2[(size_t)s2 * 8 + sub]);
        }

        float2 x01 = __half22float2(u2h(xv0.x));
        float2 x23 = __half22float2(u2h(xv0.y));
        float4 xv = make_float4(x01.x, x01.y, x23.x, x23.y);
        float2 e01 = __half22float2(u2h(ea0.x));
        float2 e23 = __half22float2(u2h(ea0.y));
        float2 e45 = __half22float2(u2h(ea0.z));
        float2 e67 = __half22float2(u2h(ea0.w));

        float4 a = make_float4(xv.x + xrv.x, xv.y + xrv.y, xv.z + xrv.z, xv.w + xrv.w);
        a.x += e01.x*w4[0].x + e01.y*w4[1].x + e23.x*w4[2].x + e23.y*w4[3].x
             + e45.x*w4[4].x + e45.y*w4[5].x + e67.x*w4[6].x + e67.y*w4[7].x;
        a.y += e01.x*w4[0].y + e01.y*w4[1].y + e23.x*w4[2].y + e23.y*w4[3].y
             + e45.x*w4[4].y + e45.y*w4[5].y + e67.x*w4[6].y + e67.y*w4[7].y;
        a.z += e01.x*w4[0].z + e01.y*w4[1].z + e23.x*w4[2].z + e23.y*w4[3].z
             + e45.x*w4[4].z + e45.y*w4[5].z + e67.x*w4[6].z + e67.y*w4[7].z;
        a.w += e01.x*w4[0].w + e01.y*w4[1].w + e23.x*w4[2].w + e23.y*w4[3].w
             + e45.x*w4[4].w + e45.y*w4[5].w + e67.x*w4[6].w + e67.y*w4[7].w;

        float t = lrelu(a.x)*at4.x + lrelu(a.y)*at4.y
                + lrelu(a.z)*at4.z + lrelu(a.w)*at4.w;
        t += __shfl_xor_sync(gmask, t, 1);
        t += __shfl_xor_sync(gmask, t, 2);
        t += __shfl_xor_sync(gmask, t, 4);

        float p = __expf(t);
        ssum += p;
        acc.x += p * xv.x; acc.y += p * xv.y;
        acc.z += p * xv.z; acc.w += p * xv.w;

        ea0 = ea1; xv0 = xv1;
        ea1 = ea2; xv1 = xv2;
    }

    float inv = 1.0f / (ssum + 1e-16f);
    float4 b = __ldg(&reinterpret_cast<const float4*>(bias)[sub]);
    float4 o;
    o.x = eluf(acc.x * inv + b.x);
    o.y = eluf(acc.y * inv + b.y);
    o.z = eluf(acc.z * inv + b.z);
    o.w = eluf(acc.w * inv + b.w);

    // fused global mean-pool accumulation
    int g = __ldg(&batch[node]);
    atomAdd4(reinterpret_cast<float4*>(gsum) + (size_t)g * 8 + sub, o);
    if (sub == 0) atomicAdd(&gcnt[g], 1.0f);
}

// ---------------- MLP head ---------------------------------------------------
__global__ void k_fc(const float* __restrict__ gsum, const float* __restrict__ gcnt,
                     const float* __restrict__ w1, const float* __restrict__ b1,
                     const float* __restrict__ w2, const float* __restrict__ b2,
                     float* __restrict__ out) {
    int g = threadIdx.x;
    if (g >= GGR) return;
    float inv = 1.0f / fmaxf(gcnt[g], 1.0f);
    float f[HIDC];
    #pragma unroll
    for (int c = 0; c < HIDC; c++) f[c] = gsum[g * HIDC + c] * inv;
    float o[OUTC] = { b2[0], b2[1], b2[2], b2[3] };
    for (int k = 0; k < 2 * HIDC; k++) {
        float h1 = b1[k];
        #pragma unroll
        for (int c = 0; c < HIDC; c++) h1 += f[c] * __ldg(&w1[c * 2 * HIDC + k]);
        h1 = eluf(h1);
        #pragma unroll
        for (int j = 0; j < OUTC; j++) o[j] += h1 * __ldg(&w2[k * OUTC + j]);
    }
    #pragma unroll
    for (int j = 0; j < OUTC; j++) out[g * OUTC + j] = o[j];
}

// ---------------- host launcher ----------------------------------------------
static void fill_f(float* p, float v, size_t n) {
    int n4 = (int)(n / 4);
    k_fill4<<<(n4 + 255) / 256, 256>>>(reinterpret_cast<float4*>(p), v, n4);
}

extern "C" void kernel_launch(void* const* d_in, const int* in_sizes, int n_in,
                              void* d_out, int out_size) {
    const float* x     = (const float*)d_in[0];
    const int*   eidx  = (const int*)  d_in[1];
    const float* eattr = (const float*)d_in[2];
    const int*   batch = (const int*)  d_in[3];
    const float *wl1=(const float*)d_in[4],  *bl1=(const float*)d_in[5];
    const float *wr1=(const float*)d_in[6],  *br1=(const float*)d_in[7];
    const float *we1=(const float*)d_in[8],  *att1=(const float*)d_in[9],  *bc1=(const float*)d_in[10];
    const float *wl2=(const float*)d_in[11], *bl2=(const float*)d_in[12];
    const float *wr2=(const float*)d_in[13], *br2=(const float*)d_in[14];
    const float *we2=(const float*)d_in[15], *att2=(const float*)d_in[16], *bc2=(const float*)d_in[17];
    const float *wl3=(const float*)d_in[18], *bl3=(const float*)d_in[19];
    const float *wr3=(const float*)d_in[20], *br3=(const float*)d_in[21];
    const float *we3=(const float*)d_in[22], *att3=(const float*)d_in[23], *bc3=(const float*)d_in[24];
    const float *w_fc1=(const float*)d_in[25], *b_fc1=(const float*)d_in[26];
    const float *w_fc2=(const float*)d_in[27], *b_fc2=(const float*)d_in[28];

    const int* src = eidx;
    const int* dst = eidx + EE;

    float *xr, *loop, *gsum, *gcnt;
    __half *xlh, *hinh, *wh1, *wh2, *wh3;
    uint4* peah;
    int *deg, *off, *cur, *psrc;
    cudaGetSymbolAddress((void**)&xlh,  d_xlh);
    cudaGetSymbolAddress((void**)&xr,   d_xr);
    cudaGetSymbolAddress((void**)&hinh, d_hinh);
    cudaGetSymbolAddress((void**)&loop, d_loop);
    cudaGetSymbolAddress((void**)&deg,  d_deg);
    cudaGetSymbolAddress((void**)&off,  d_off);
    cudaGetSymbolAddress((void**)&cur,  d_cur);
    cudaGetSymbolAddress((void**)&psrc, d_psrc);
    cudaGetSymbolAddress((void**)&peah, d_peah);
    cudaGetSymbolAddress((void**)&wh1,  d_wh1);
    cudaGetSymbolAddress((void**)&wh2,  d_wh2);
    cudaGetSymbolAddress((void**)&wh3,  d_wh3);
    cudaGetSymbolAddress((void**)&gsum, d_gsum);
    cudaGetSymbolAddress((void**)&gcnt, d_gcnt);

    const int AB4 = (NN + 7) / 8;
    const int AB1 = (NN + 31) / 32;

    // ---- CSR build ----
    fill_f((float*)deg, 0.0f, NN);
    fill_f(loop, 0.0f, (size_t)NN * EDIMC);
    k_hist<<<(EE + 255) / 256, 256>>>(dst, eattr, deg, loop);
    k_loop_div<<<(NN * 2 + 255) / 256, 256>>>(loop, deg);
    k_scan<<<1, 1024>>>(deg, off, cur);
    k_self<<<(NN + 255) / 256, 256>>>(off, loop, psrc, peah);
    k_scatter<<<(EE + 255) / 256, 256>>>(src, dst, eattr, cur, psrc, peah);

    // ---- weight conversions (fp16) ----
    k_cvt_w<IN_F, HCC><<<(IN_F * 2 * HCC + 255) / 256, 256>>>(wl1, wr1, wh1);
    k_cvt_w<HCC, HCC><<<(HCC * 2 * HCC + 255) / 256, 256>>>(wl2, wr2, wh2);
    k_cvt_w<HCC, HIDC><<<(HCC * 2 * HIDC + 255) / 256, 256>>>(wl3, wr3, wh3);

    // ---- layer 1: IN=16 -> 4x32 (fp32 input converted in-kernel) ----
    k_transform_mma<IN_F, 2 * HCC, 32, true><<<(NN + 31) / 32, 256>>>(x, wh1, bl1, br1, xlh, xr);
    k_gat_csr4<<<AB4, 256>>>(off, psrc, peah, we1, att1, bc1, xlh, xr, hinh);

    // ---- layer 2: 128 -> 4x32 ----
    k_transform_mma<HCC, 2 * HCC, 32, false><<<(NN + 31) / 32, 256>>>(hinh, wh2, bl2, br2, xlh, xr);
    k_gat_csr4<<<AB4, 256>>>(off, psrc, peah, we2, att2, bc2, xlh, xr, hinh);

    // ---- layer 3: 128 -> 1x32, agg fused with mean-pool ----
    k_transform_mma<HCC, 2 * HIDC, 64, false><<<(NN + 63) / 64, 128>>>(hinh, wh3, bl3, br3, xlh, xr);
    fill_f(gsum, 0.0f, (size_t)GGR * HIDC);
    fill_f(gcnt, 0.0f, GGR);
    k_gat_csr1_pool<<<AB1, 256>>>(off, psrc, peah, we3, att3, bc3, batch, xlh, xr, gsum, gcnt);

    // ---- MLP head ----
    k_fc<<<1, 128>>>(gsum, gcnt, w_fc1, b_fc1, w_fc2, b_fc2, (float*)d_out);
}